// round 1
// baseline (speedup 1.0000x reference)
#include <cuda_runtime.h>
#include <math.h>

#define B_ 2
#define T_ 2048
#define C_ 1024
#define H_ 16
#define D_ 64

// ---- scratch (no cudaMalloc allowed) ----
__device__ float g_q[(size_t)B_ * H_ * T_ * D_];          // 16.8 MB  [b][h][t][d]
__device__ float g_k[(size_t)B_ * H_ * T_ * D_];          // 16.8 MB
__device__ float g_v[(size_t)B_ * H_ * T_ * D_];          // 16.8 MB
__device__ float g_s[(size_t)B_ * H_ * T_ * T_];          // 536.9 MB [b][h][q][k]
__device__ float g_o[(size_t)B_ * T_ * C_];               // 16.8 MB  [b][t][h*64+d]

// ---------------------------------------------------------------------------
// Register-blocked SGEMM:  C[m,n] = sum_k A[m,k] * B[n,k]   (NT)
//                      or  C[m,n] = sum_k A[m,k] * B[k,n]   (NN, B_IS_KN)
// BM=128, BN=64, BK=16, 256 threads, 8x4 per-thread tile.
// All problem dims here are exact multiples of the tile dims -> no guards.
//
// MODE 0: QKV projection epilogue  -> out[((b*H+h)*T+t)*D+d], m=b*T+t, n=h*D+d
// MODE 1: S epilogue               -> out[z*T*T + m*T + n] * 8.0f
// MODE 2: PV epilogue              -> out[(b*T+m)*C + h*D + n],  z=b*H+h
// MODE 3: final epilogue           -> out[m*C + n] + bias[n]
// ---------------------------------------------------------------------------
#define BM 128
#define BN 64
#define BKK 16
#define TM 8
#define TN 4

template <int MODE, bool B_IS_KN>
__global__ __launch_bounds__(256) void gemm_kernel(
    const float* __restrict__ A, const float* __restrict__ Bmat,
    float* __restrict__ Cout, const float* __restrict__ bias,
    int K, int lda, int ldb,
    long long strideA, long long strideB)
{
    __shared__ float As[BKK][BM];
    __shared__ float Bs[BKK][BN];

    const int z = blockIdx.z;
    const float* Ab = A + (long long)z * strideA;
    const float* Bb = Bmat + (long long)z * strideB;

    const int m0 = blockIdx.y * BM;
    const int n0 = blockIdx.x * BN;
    const int tid = threadIdx.x;
    const int tx = tid & 15;   // 0..15 -> n
    const int ty = tid >> 4;   // 0..15 -> m

    float acc[TM][TN];
#pragma unroll
    for (int i = 0; i < TM; i++)
#pragma unroll
        for (int j = 0; j < TN; j++) acc[i][j] = 0.0f;

    for (int k0 = 0; k0 < K; k0 += BKK) {
        // ---- load A tile (128 rows x 16 cols), transpose into As[k][m] ----
        {
            const int r  = tid >> 2;          // 0..63
            const int c4 = (tid & 3) * 4;     // 0,4,8,12
            float4 v0 = *(const float4*)(Ab + (long long)(m0 + r) * lda + k0 + c4);
            float4 v1 = *(const float4*)(Ab + (long long)(m0 + r + 64) * lda + k0 + c4);
            As[c4 + 0][r] = v0.x; As[c4 + 1][r] = v0.y;
            As[c4 + 2][r] = v0.z; As[c4 + 3][r] = v0.w;
            As[c4 + 0][r + 64] = v1.x; As[c4 + 1][r + 64] = v1.y;
            As[c4 + 2][r + 64] = v1.z; As[c4 + 3][r + 64] = v1.w;
        }
        // ---- load B tile into Bs[k][n] ----
        if (B_IS_KN) {
            const int kk = tid >> 4;          // 0..15
            const int c4 = (tid & 15) * 4;    // 0..60
            float4 v = *(const float4*)(Bb + (long long)(k0 + kk) * ldb + n0 + c4);
            *(float4*)&Bs[kk][c4] = v;
        } else {
            const int r  = tid >> 2;          // 0..63
            const int c4 = (tid & 3) * 4;     // 0,4,8,12
            float4 v = *(const float4*)(Bb + (long long)(n0 + r) * ldb + k0 + c4);
            Bs[c4 + 0][r] = v.x; Bs[c4 + 1][r] = v.y;
            Bs[c4 + 2][r] = v.z; Bs[c4 + 3][r] = v.w;
        }
        __syncthreads();

#pragma unroll
        for (int kk = 0; kk < BKK; kk++) {
            float a[TM], b[TN];
#pragma unroll
            for (int i = 0; i < TM; i++) a[i] = As[kk][ty * TM + i];
#pragma unroll
            for (int j = 0; j < TN; j++) b[j] = Bs[kk][tx * TN + j];
#pragma unroll
            for (int i = 0; i < TM; i++)
#pragma unroll
                for (int j = 0; j < TN; j++)
                    acc[i][j] = fmaf(a[i], b[j], acc[i][j]);
        }
        __syncthreads();
    }

    // ---- epilogue ----
    const int n = n0 + tx * TN;  // contiguous span of 4, never crosses a 64-boundary
#pragma unroll
    for (int i = 0; i < TM; i++) {
        const int m = m0 + ty * TM + i;
        float4 f;
        f.x = acc[i][0]; f.y = acc[i][1]; f.z = acc[i][2]; f.w = acc[i][3];
        if (MODE == 0) {
            const int b = m >> 11;        // m / T_
            const int t = m & (T_ - 1);
            const int h = n >> 6;         // n / D_
            const int d = n & (D_ - 1);
            *(float4*)&Cout[(((long long)(b * H_ + h) * T_ + t) * D_) + d] = f;
        } else if (MODE == 1) {
            f.x *= 8.0f; f.y *= 8.0f; f.z *= 8.0f; f.w *= 8.0f;
            *(float4*)&Cout[(long long)z * T_ * T_ + (long long)m * T_ + n] = f;
        } else if (MODE == 2) {
            const int b = z / H_;
            const int h = z % H_;
            *(float4*)&Cout[((long long)(b * T_ + m)) * C_ + h * D_ + n] = f;
        } else {
            f.x += bias[n + 0]; f.y += bias[n + 1];
            f.z += bias[n + 2]; f.w += bias[n + 3];
            *(float4*)&Cout[(long long)m * C_ + n] = f;
        }
    }
}

// ---------------------------------------------------------------------------
// Head-axis softmax (reference quirk: softmax over dim=1 == H).
// One thread per (b,q,k); reads/writes 16 values at stride T*T. Coalesced in k.
// ---------------------------------------------------------------------------
__global__ __launch_bounds__(256) void softmax_head_kernel(float* __restrict__ s)
{
    const long long idx = (long long)blockIdx.x * blockDim.x + threadIdx.x; // over B*T*T
    const long long hs = (long long)T_ * T_;
    const int kk = (int)(idx & (T_ - 1));
    const long long bq = idx >> 11;           // b*T + q
    const int b = (int)(bq >> 11);
    const int q = (int)(bq & (T_ - 1));
    const long long base = (((long long)b * H_) * T_ + q) * T_ + kk;

    float v[H_];
    float mx = -1e30f;
#pragma unroll
    for (int h = 0; h < H_; h++) {
        v[h] = s[base + (long long)h * hs];
        mx = fmaxf(mx, v[h]);
    }
    float sum = 0.0f;
#pragma unroll
    for (int h = 0; h < H_; h++) {
        v[h] = __expf(v[h] - mx);
        sum += v[h];
    }
    const float inv = 1.0f / sum;
#pragma unroll
    for (int h = 0; h < H_; h++)
        s[base + (long long)h * hs] = v[h] * inv;
}

// ---------------------------------------------------------------------------
extern "C" void kernel_launch(void* const* d_in, const int* in_sizes, int n_in,
                              void* d_out, int out_size)
{
    const float* query_src = (const float*)d_in[0];
    const float* key_src   = (const float*)d_in[1];
    const float* value_src = (const float*)d_in[2];
    const float* Wq        = (const float*)d_in[3];
    const float* Wk        = (const float*)d_in[4];
    const float* Wv        = (const float*)d_in[5];
    const float* Wo        = (const float*)d_in[6];
    const float* bo        = (const float*)d_in[7];
    float* out = (float*)d_out;

    float *q, *k, *v, *s, *o;
    cudaGetSymbolAddress((void**)&q, g_q);
    cudaGetSymbolAddress((void**)&k, g_k);
    cudaGetSymbolAddress((void**)&v, g_v);
    cudaGetSymbolAddress((void**)&s, g_s);
    cudaGetSymbolAddress((void**)&o, g_o);

    const dim3 blk(256);

    // Pass 1: projections  y = x @ W^T, written in [b,h,t,d]
    {
        dim3 grid(C_ / BN, (B_ * T_) / BM, 1);
        gemm_kernel<0, false><<<grid, blk>>>(query_src, Wq, q, nullptr, C_, C_, C_, 0, 0);
        gemm_kernel<0, false><<<grid, blk>>>(key_src,   Wk, k, nullptr, C_, C_, C_, 0, 0);
        gemm_kernel<0, false><<<grid, blk>>>(value_src, Wv, v, nullptr, C_, C_, C_, 0, 0);
    }

    // Pass 2: S[b,h,q,k] = 8 * q . k   (batched over z = b*H+h)
    {
        dim3 grid(T_ / BN, T_ / BM, B_ * H_);
        gemm_kernel<1, false><<<grid, blk>>>(q, k, s, nullptr, D_, D_, D_,
                                             (long long)T_ * D_, (long long)T_ * D_);
    }

    // Pass 3: softmax over the HEAD axis (in place)
    {
        const long long total = (long long)B_ * T_ * T_;
        softmax_head_kernel<<<(unsigned)(total / 256), blk>>>(s);
    }

    // Pass 4: O[b,h,q,d] = P @ V  -> written as [b][q][h*64+d]
    {
        dim3 grid(D_ / BN, T_ / BM, B_ * H_);   // D_/BN == 1
        gemm_kernel<2, true><<<grid, blk>>>(s, v, o, nullptr, T_, T_, D_,
                                            (long long)T_ * T_, (long long)T_ * D_);
    }

    // Pass 5: out = O @ Wo^T + bo
    {
        dim3 grid(C_ / BN, (B_ * T_) / BM, 1);
        gemm_kernel<3, false><<<grid, blk>>>(o, Wo, out, bo, C_, C_, C_, 0, 0);
    }
}

// round 3
// speedup vs baseline: 1.1067x; 1.1067x over previous
#include <cuda_runtime.h>
#include <math.h>

#define B_ 2
#define T_ 2048
#define C_ 1024
#define H_ 16
#define D_ 64

// ---- scratch (no cudaMalloc allowed) ----
__device__ float g_q[(size_t)B_ * H_ * T_ * D_];          // [b][h][t][d]
__device__ float g_k[(size_t)B_ * H_ * T_ * D_];
__device__ float g_v[(size_t)B_ * H_ * T_ * D_];
__device__ float g_s[(size_t)B_ * H_ * T_ * T_];          // [b][h][q][k]
__device__ float g_o[(size_t)B_ * T_ * C_];               // [b][t][h*64+d]

// ---------------------------------------------------------------------------
// gemm128: C[m,n] = sum_k A[m,k]*B[n,k] (NT) or A[m,k]*B[k,n] (NN)
// BM=BN=128, BK=16, 256 threads, 8x8 per thread, double-buffered smem.
// MODE 0: QKV projection epilogue  -> out[((b*H+h)*T+t)*D+d]
// MODE 1: S epilogue               -> out[z*T*T + m*T + n] * 8.0f
// MODE 3: final epilogue           -> out[m*C + n] + bias[n]
// ---------------------------------------------------------------------------
template <int MODE, bool B_IS_KN>
__global__ __launch_bounds__(256, 2) void gemm128(
    const float* __restrict__ A, const float* __restrict__ Bmat,
    float* __restrict__ Cout, const float* __restrict__ bias,
    int K, int lda, int ldb,
    long long strideA, long long strideB)
{
    __shared__ float As[2][16][128];
    __shared__ float Bs[2][16][128];

    const int z = blockIdx.z;
    const float* Ab = A + (long long)z * strideA;
    const float* Bb = Bmat + (long long)z * strideB;

    const int m0 = blockIdx.y * 128;
    const int n0 = blockIdx.x * 128;
    const int tid = threadIdx.x;
    const int tx = tid & 15;   // n
    const int ty = tid >> 4;   // m

    // loader indices (transpose loads: 64 rows x 16 cols per half)
    const int lr = tid >> 2;          // 0..63
    const int lc = (tid & 3) * 4;     // 0,4,8,12
    // NN B loader
    const int bk = tid >> 5;          // 0..7
    const int bc = (tid & 31) * 4;    // 0..124

    float4 pa0, pa1, pb0, pb1;

    auto loadA = [&](int k0) {
        pa0 = *(const float4*)(Ab + (long long)(m0 + lr) * lda + k0 + lc);
        pa1 = *(const float4*)(Ab + (long long)(m0 + lr + 64) * lda + k0 + lc);
    };
    auto loadB = [&](int k0) {
        if (B_IS_KN) {
            pb0 = *(const float4*)(Bb + (long long)(k0 + bk) * ldb + n0 + bc);
            pb1 = *(const float4*)(Bb + (long long)(k0 + bk + 8) * ldb + n0 + bc);
        } else {
            pb0 = *(const float4*)(Bb + (long long)(n0 + lr) * ldb + k0 + lc);
            pb1 = *(const float4*)(Bb + (long long)(n0 + lr + 64) * ldb + k0 + lc);
        }
    };
    auto stage = [&](int buf) {
        As[buf][lc + 0][lr] = pa0.x; As[buf][lc + 1][lr] = pa0.y;
        As[buf][lc + 2][lr] = pa0.z; As[buf][lc + 3][lr] = pa0.w;
        As[buf][lc + 0][lr + 64] = pa1.x; As[buf][lc + 1][lr + 64] = pa1.y;
        As[buf][lc + 2][lr + 64] = pa1.z; As[buf][lc + 3][lr + 64] = pa1.w;
        if (B_IS_KN) {
            *(float4*)&Bs[buf][bk][bc]     = pb0;
            *(float4*)&Bs[buf][bk + 8][bc] = pb1;
        } else {
            Bs[buf][lc + 0][lr] = pb0.x; Bs[buf][lc + 1][lr] = pb0.y;
            Bs[buf][lc + 2][lr] = pb0.z; Bs[buf][lc + 3][lr] = pb0.w;
            Bs[buf][lc + 0][lr + 64] = pb1.x; Bs[buf][lc + 1][lr + 64] = pb1.y;
            Bs[buf][lc + 2][lr + 64] = pb1.z; Bs[buf][lc + 3][lr + 64] = pb1.w;
        }
    };

    float acc[8][8];
#pragma unroll
    for (int i = 0; i < 8; i++)
#pragma unroll
        for (int j = 0; j < 8; j++) acc[i][j] = 0.0f;

    auto compute = [&](int buf) {
#pragma unroll
        for (int kk = 0; kk < 16; kk++) {
            float4 a0 = *(const float4*)&As[buf][kk][ty * 8];
            float4 a1 = *(const float4*)&As[buf][kk][ty * 8 + 4];
            float4 b0 = *(const float4*)&Bs[buf][kk][tx * 8];
            float4 b1 = *(const float4*)&Bs[buf][kk][tx * 8 + 4];
            float a[8] = {a0.x, a0.y, a0.z, a0.w, a1.x, a1.y, a1.z, a1.w};
            float b[8] = {b0.x, b0.y, b0.z, b0.w, b1.x, b1.y, b1.z, b1.w};
#pragma unroll
            for (int i = 0; i < 8; i++)
#pragma unroll
                for (int j = 0; j < 8; j++)
                    acc[i][j] = fmaf(a[i], b[j], acc[i][j]);
        }
    };

    loadA(0); loadB(0);
    stage(0);
    __syncthreads();
    int buf = 0;
    for (int k0 = 16; k0 < K; k0 += 16) {
        loadA(k0); loadB(k0);
        compute(buf);
        stage(buf ^ 1);
        __syncthreads();
        buf ^= 1;
    }
    compute(buf);

    // ---- epilogue ----
    const int n = n0 + tx * 8;   // 8-span, never crosses a 64-boundary
#pragma unroll
    for (int i = 0; i < 8; i++) {
        const int m = m0 + ty * 8 + i;
        float4 lo, hi;
        lo.x = acc[i][0]; lo.y = acc[i][1]; lo.z = acc[i][2]; lo.w = acc[i][3];
        hi.x = acc[i][4]; hi.y = acc[i][5]; hi.z = acc[i][6]; hi.w = acc[i][7];
        if (MODE == 0) {
            const int b = m >> 11;
            const int t = m & (T_ - 1);
            const int h = n >> 6;
            const int d = n & (D_ - 1);
            long long base = (((long long)(b * H_ + h) * T_ + t) * D_) + d;
            *(float4*)&Cout[base]     = lo;
            *(float4*)&Cout[base + 4] = hi;
        } else if (MODE == 1) {
            lo.x *= 8.0f; lo.y *= 8.0f; lo.z *= 8.0f; lo.w *= 8.0f;
            hi.x *= 8.0f; hi.y *= 8.0f; hi.z *= 8.0f; hi.w *= 8.0f;
            long long base = (long long)z * T_ * T_ + (long long)m * T_ + n;
            *(float4*)&Cout[base]     = lo;
            *(float4*)&Cout[base + 4] = hi;
        } else {
            lo.x += bias[n + 0]; lo.y += bias[n + 1];
            lo.z += bias[n + 2]; lo.w += bias[n + 3];
            hi.x += bias[n + 4]; hi.y += bias[n + 5];
            hi.z += bias[n + 6]; hi.w += bias[n + 7];
            long long base = (long long)m * C_ + n;
            *(float4*)&Cout[base]     = lo;
            *(float4*)&Cout[base + 4] = hi;
        }
    }
}

// ---------------------------------------------------------------------------
// gemm_pv: O[b,h,q,d] = P @ V  (NN), M=2048, N=64, K=2048 per z=b*H+h.
// BM=128, BN=64, BK=32, 256 threads, 8x4 per thread, double-buffered.
// Writes out[(b*T+m)*C + h*64 + n].
// ---------------------------------------------------------------------------
__global__ __launch_bounds__(256, 2) void gemm_pv(
    const float* __restrict__ P, const float* __restrict__ V,
    float* __restrict__ Cout)
{
    __shared__ float As[2][32][128];
    __shared__ float Bs[2][32][64];

    const int z = blockIdx.z;
    const float* Ab = P + (long long)z * T_ * T_;
    const float* Bb = V + (long long)z * T_ * D_;

    const int m0 = blockIdx.y * 128;
    const int tid = threadIdx.x;
    const int tx = tid & 15;   // n: tx*4
    const int ty = tid >> 4;   // m: ty*8

    const int ar = tid >> 3;          // 0..31  (rows ar, ar+32, ar+64, ar+96)
    const int ac = (tid & 7) * 4;     // 0..28
    const int bk = tid >> 4;          // 0..15  (rows bk, bk+16)
    const int bc = (tid & 15) * 4;    // 0..60

    float4 pa[4], pb[2];

    auto loadA = [&](int k0) {
#pragma unroll
        for (int i = 0; i < 4; i++)
            pa[i] = *(const float4*)(Ab + (long long)(m0 + ar + i * 32) * T_ + k0 + ac);
    };
    auto loadB = [&](int k0) {
#pragma unroll
        for (int i = 0; i < 2; i++)
            pb[i] = *(const float4*)(Bb + (long long)(k0 + bk + i * 16) * D_ + bc);
    };
    auto stage = [&](int buf) {
#pragma unroll
        for (int i = 0; i < 4; i++) {
            As[buf][ac + 0][ar + i * 32] = pa[i].x;
            As[buf][ac + 1][ar + i * 32] = pa[i].y;
            As[buf][ac + 2][ar + i * 32] = pa[i].z;
            As[buf][ac + 3][ar + i * 32] = pa[i].w;
        }
        *(float4*)&Bs[buf][bk][bc]      = pb[0];
        *(float4*)&Bs[buf][bk + 16][bc] = pb[1];
    };

    float acc[8][4];
#pragma unroll
    for (int i = 0; i < 8; i++)
#pragma unroll
        for (int j = 0; j < 4; j++) acc[i][j] = 0.0f;

    auto compute = [&](int buf) {
#pragma unroll
        for (int kk = 0; kk < 32; kk++) {
            float4 a0 = *(const float4*)&As[buf][kk][ty * 8];
            float4 a1 = *(const float4*)&As[buf][kk][ty * 8 + 4];
            float4 b0 = *(const float4*)&Bs[buf][kk][tx * 4];
            float a[8] = {a0.x, a0.y, a0.z, a0.w, a1.x, a1.y, a1.z, a1.w};
            float b[4] = {b0.x, b0.y, b0.z, b0.w};
#pragma unroll
            for (int i = 0; i < 8; i++)
#pragma unroll
                for (int j = 0; j < 4; j++)
                    acc[i][j] = fmaf(a[i], b[j], acc[i][j]);
        }
    };

    loadA(0); loadB(0);
    stage(0);
    __syncthreads();
    int buf = 0;
    for (int k0 = 32; k0 < T_; k0 += 32) {
        loadA(k0); loadB(k0);
        compute(buf);
        stage(buf ^ 1);
        __syncthreads();
        buf ^= 1;
    }
    compute(buf);

    const int b = z >> 4;
    const int h = z & 15;
    const int n = tx * 4;
#pragma unroll
    for (int i = 0; i < 8; i++) {
        const int m = m0 + ty * 8 + i;
        float4 f;
        f.x = acc[i][0]; f.y = acc[i][1]; f.z = acc[i][2]; f.w = acc[i][3];
        *(float4*)&Cout[((long long)(b * T_ + m)) * C_ + h * D_ + n] = f;
    }
}

// ---------------------------------------------------------------------------
// Head-axis softmax (reference quirk: softmax over dim=1 == H).
// ---------------------------------------------------------------------------
__global__ __launch_bounds__(256) void softmax_head_kernel(float* __restrict__ s)
{
    const long long idx = (long long)blockIdx.x * blockDim.x + threadIdx.x;
    const long long hs = (long long)T_ * T_;
    const int kk = (int)(idx & (T_ - 1));
    const long long bq = idx >> 11;
    const int b = (int)(bq >> 11);
    const int q = (int)(bq & (T_ - 1));
    const long long base = (((long long)b * H_) * T_ + q) * T_ + kk;

    float v[H_];
    float mx = -1e30f;
#pragma unroll
    for (int h = 0; h < H_; h++) {
        v[h] = s[base + (long long)h * hs];
        mx = fmaxf(mx, v[h]);
    }
    float sum = 0.0f;
#pragma unroll
    for (int h = 0; h < H_; h++) {
        v[h] = __expf(v[h] - mx);
        sum += v[h];
    }
    const float inv = 1.0f / sum;
#pragma unroll
    for (int h = 0; h < H_; h++)
        s[base + (long long)h * hs] = v[h] * inv;
}

// ---------------------------------------------------------------------------
extern "C" void kernel_launch(void* const* d_in, const int* in_sizes, int n_in,
                              void* d_out, int out_size)
{
    const float* query_src = (const float*)d_in[0];
    const float* key_src   = (const float*)d_in[1];
    const float* value_src = (const float*)d_in[2];
    const float* Wq        = (const float*)d_in[3];
    const float* Wk        = (const float*)d_in[4];
    const float* Wv        = (const float*)d_in[5];
    const float* Wo        = (const float*)d_in[6];
    const float* bo        = (const float*)d_in[7];
    float* out = (float*)d_out;

    float *q, *k, *v, *s, *o;
    cudaGetSymbolAddress((void**)&q, g_q);
    cudaGetSymbolAddress((void**)&k, g_k);
    cudaGetSymbolAddress((void**)&v, g_v);
    cudaGetSymbolAddress((void**)&s, g_s);
    cudaGetSymbolAddress((void**)&o, g_o);

    const dim3 blk(256);

    // Pass 1: projections  y = x @ W^T  -> [b,h,t,d]
    {
        dim3 grid(C_ / 128, (B_ * T_) / 128, 1);
        gemm128<0, false><<<grid, blk>>>(query_src, Wq, q, nullptr, C_, C_, C_, 0, 0);
        gemm128<0, false><<<grid, blk>>>(key_src,   Wk, k, nullptr, C_, C_, C_, 0, 0);
        gemm128<0, false><<<grid, blk>>>(value_src, Wv, v, nullptr, C_, C_, C_, 0, 0);
    }

    // Pass 2: S[b,h,q,k] = 8 * q . k
    {
        dim3 grid(T_ / 128, T_ / 128, B_ * H_);
        gemm128<1, false><<<grid, blk>>>(q, k, s, nullptr, D_, D_, D_,
                                         (long long)T_ * D_, (long long)T_ * D_);
    }

    // Pass 3: softmax over HEAD axis (in place)
    {
        const long long total = (long long)B_ * T_ * T_;
        softmax_head_kernel<<<(unsigned)(total / 256), blk>>>(s);
    }

    // Pass 4: O = P @ V  -> [b][q][h*64+d]
    {
        dim3 grid(1, T_ / 128, B_ * H_);
        gemm_pv<<<grid, blk>>>(s, v, o);
    }

    // Pass 5: out = O @ Wo^T + bo
    {
        dim3 grid(C_ / 128, (B_ * T_) / 128, 1);
        gemm128<3, false><<<grid, blk>>>(o, Wo, out, bo, C_, C_, C_, 0, 0);
    }
}

// round 9
// speedup vs baseline: 1.6471x; 1.4883x over previous
#include <cuda_runtime.h>
#include <cstdint>

#define B_ 2
#define T_ 2048
#define C_ 1024
#define H_ 16
#define D_ 64

// ---- scratch (no cudaMalloc allowed) ----
__device__ float g_q[(size_t)B_ * H_ * T_ * D_];          // [b][h][t][d]
__device__ float g_k[(size_t)B_ * H_ * T_ * D_];          // [b][h][t][d]
__device__ float g_v[(size_t)B_ * H_ * D_ * T_];          // [b][h][d][t]  (TRANSPOSED)
__device__ float g_s[(size_t)B_ * H_ * T_ * T_];          // [b][h][q][k]
__device__ float g_o[(size_t)B_ * T_ * C_];               // [b][t][h*64+d]

__device__ __forceinline__ float tf32_rna(float x) {
    float y;
    asm("cvt.rna.tf32.f32 %0, %1;" : "=f"(y) : "f"(x));
    return y;
}

// m16n8k8 tf32 mma (baseline PTX, maps to HMMA on sm_103)
#define MMA_TF32(c, a, b)                                                        \
    asm volatile("mma.sync.aligned.m16n8k8.row.col.f32.tf32.tf32.f32 "           \
                 "{%0,%1,%2,%3}, {%4,%5,%6,%7}, {%8,%9}, {%0,%1,%2,%3};"         \
                 : "+f"((c)[0]), "+f"((c)[1]), "+f"((c)[2]), "+f"((c)[3])        \
                 : "r"((a)[0]), "r"((a)[1]), "r"((a)[2]), "r"((a)[3]),           \
                   "r"((b)[0]), "r"((b)[1]))

// ============================================================================
// Tensor-core GEMM:  C[m,n] = sum_k A[m,k] * B[n,k]   (NT; B row n, col k)
// CTA: 128 x BN x 32, 256 thr (8 warps).
//   BN=128: warps 2m x 4n (warp tile 64x32);  BN=64: warps 4m x 2n (32x32).
// SPLIT: 2-term tf32 split (hi*hi + hi*lo + lo*hi) -> fp32-class accuracy.
// MODE 0: QK proj -> out[((b*H+h)*T+t)*64+d]
// MODE 4: V proj  -> out[((b*H+h)*64+d)*T+t]   (transposed)
// MODE 1: S       -> out[z*T*T + m*T + n] * 8
// MODE 2: PV      -> out[(b*T+m)*C + h*64 + n]
// MODE 3: O proj  -> out[m*C+n] + bias[n]
// ============================================================================
template <int MODE, bool SPLIT, int BN>
__global__ __launch_bounds__(256, 2) void mma_gemm(
    const float* __restrict__ A, const float* __restrict__ Bm,
    float* __restrict__ Cout, const float* __restrict__ bias,
    int K, int lda, int ldb, long long sA, long long sB)
{
    constexpr int BM = 128, BKP = 36;
    constexpr int GM = (BN == 128) ? 2 : 4;       // warp grid (m)
    constexpr int WM = (BN == 128) ? 4 : 2;       // m16 tiles per warp
    constexpr int WN = 4;                         // n8 tiles per warp
    constexpr int NA4 = 4;                        // A float4s per thread per chunk
    constexpr int NB4 = BN / 32;                  // B float4s per thread per chunk
    constexpr int ASZ = BM * BKP;
    constexpr int BSZ = BN * BKP;

    extern __shared__ float sm[];
    float* Ah = sm;
    float* Al = Ah + (SPLIT ? ASZ : 0);
    float* Bh = Ah + (SPLIT ? 2 : 1) * ASZ;
    float* Bl = Bh + (SPLIT ? BSZ : 0);

    const int tid = threadIdx.x;
    const int w   = tid >> 5;
    const int lane = tid & 31;
    const int gid = lane >> 2;     // 0..7
    const int tig = lane & 3;      // 0..3
    const int wm = w % GM;
    const int wn = w / GM;
    const int warp_m0 = wm * WM * 16;
    const int warp_n0 = wn * WN * 8;

    const int z = blockIdx.z;
    const float* Ab = A + (long long)z * sA;
    const float* Bb = Bm + (long long)z * sB;
    const int m0 = blockIdx.y * BM;
    const int n0 = blockIdx.x * BN;

    const int ar = tid >> 3;            // 0..31
    const int ac = (tid & 7) * 4;       // 0,4,...,28

    float acc[WM][WN][4];
#pragma unroll
    for (int i = 0; i < WM; i++)
#pragma unroll
        for (int j = 0; j < WN; j++)
#pragma unroll
            for (int t = 0; t < 4; t++) acc[i][j][t] = 0.0f;

    float4 pa[NA4], pb[NB4];
    auto loadA = [&](int k0) {
#pragma unroll
        for (int i = 0; i < NA4; i++)
            pa[i] = *(const float4*)(Ab + (long long)(m0 + ar + i * 32) * lda + k0 + ac);
    };
    auto loadB = [&](int k0) {
#pragma unroll
        for (int i = 0; i < NB4; i++)
            pb[i] = *(const float4*)(Bb + (long long)(n0 + ar + i * 32) * ldb + k0 + ac);
    };
    auto stage = [&]() {
#pragma unroll
        for (int i = 0; i < NA4; i++) {
            const int r = ar + i * 32;
            float4 h4, l4;
            h4.x = tf32_rna(pa[i].x); h4.y = tf32_rna(pa[i].y);
            h4.z = tf32_rna(pa[i].z); h4.w = tf32_rna(pa[i].w);
            *(float4*)&Ah[r * BKP + ac] = h4;
            if (SPLIT) {
                l4.x = tf32_rna(pa[i].x - h4.x); l4.y = tf32_rna(pa[i].y - h4.y);
                l4.z = tf32_rna(pa[i].z - h4.z); l4.w = tf32_rna(pa[i].w - h4.w);
                *(float4*)&Al[r * BKP + ac] = l4;
            }
        }
#pragma unroll
        for (int i = 0; i < NB4; i++) {
            const int r = ar + i * 32;
            float4 h4, l4;
            h4.x = tf32_rna(pb[i].x); h4.y = tf32_rna(pb[i].y);
            h4.z = tf32_rna(pb[i].z); h4.w = tf32_rna(pb[i].w);
            *(float4*)&Bh[r * BKP + ac] = h4;
            if (SPLIT) {
                l4.x = tf32_rna(pb[i].x - h4.x); l4.y = tf32_rna(pb[i].y - h4.y);
                l4.z = tf32_rna(pb[i].z - h4.z); l4.w = tf32_rna(pb[i].w - h4.w);
                *(float4*)&Bl[r * BKP + ac] = l4;
            }
        }
    };

    const uint32_t* Ahu = (const uint32_t*)Ah;
    const uint32_t* Alu = (const uint32_t*)Al;
    const uint32_t* Bhu = (const uint32_t*)Bh;
    const uint32_t* Blu = (const uint32_t*)Bl;

    const int NC = K / 32;
    loadA(0); loadB(0);
    for (int c = 0; c < NC; c++) {
        __syncthreads();                 // previous compute done (no-op on c=0)
        stage();
        __syncthreads();
        if (c + 1 < NC) { loadA((c + 1) * 32); loadB((c + 1) * 32); }

#pragma unroll
        for (int ks = 0; ks < 4; ks++) {
            uint32_t bh[WN][2], bl[WN][2];
#pragma unroll
            for (int nt = 0; nt < WN; nt++) {
                const int base = (warp_n0 + nt * 8 + gid) * BKP + ks * 8 + tig;
                bh[nt][0] = Bhu[base]; bh[nt][1] = Bhu[base + 4];
                if (SPLIT) { bl[nt][0] = Blu[base]; bl[nt][1] = Blu[base + 4]; }
            }
#pragma unroll
            for (int mt = 0; mt < WM; mt++) {
                const int base = (warp_m0 + mt * 16 + gid) * BKP + ks * 8 + tig;
                uint32_t ah[4], al[4];
                ah[0] = Ahu[base];           ah[1] = Ahu[base + 8 * BKP];
                ah[2] = Ahu[base + 4];       ah[3] = Ahu[base + 8 * BKP + 4];
                if (SPLIT) {
                    al[0] = Alu[base];       al[1] = Alu[base + 8 * BKP];
                    al[2] = Alu[base + 4];   al[3] = Alu[base + 8 * BKP + 4];
                }
#pragma unroll
                for (int nt = 0; nt < WN; nt++) {
                    MMA_TF32(acc[mt][nt], ah, bh[nt]);
                    if (SPLIT) {
                        MMA_TF32(acc[mt][nt], ah, bl[nt]);
                        MMA_TF32(acc[mt][nt], al, bh[nt]);
                    }
                }
            }
        }
    }

    // ---------------- epilogue ----------------
#pragma unroll
    for (int mt = 0; mt < WM; mt++) {
#pragma unroll
        for (int nt = 0; nt < WN; nt++) {
            const int m = m0 + warp_m0 + mt * 16 + gid;
            const int n = n0 + warp_n0 + nt * 8 + tig * 2;
            const float* cc = acc[mt][nt];
            if (MODE == 0) {
                // out[((b*H+h)*T+t)*64 + d]
#pragma unroll
                for (int r = 0; r < 2; r++) {
                    const int mm = m + r * 8;
                    const int bb = mm >> 11, t = mm & (T_ - 1);
                    const int h = n >> 6, d0 = n & 63;
                    float2 f; f.x = cc[r * 2]; f.y = cc[r * 2 + 1];
                    *(float2*)&Cout[(((long long)(bb * H_ + h) * T_ + t) * D_) + d0] = f;
                }
            } else if (MODE == 4) {
                // out[((b*H+h)*64+d)*T + t]   (V transposed)
#pragma unroll
                for (int r = 0; r < 2; r++) {
                    const int mm = m + r * 8;
                    const int bb = mm >> 11, t = mm & (T_ - 1);
#pragma unroll
                    for (int jj = 0; jj < 2; jj++) {
                        const int nn = n + jj;
                        const int h = nn >> 6, d0 = nn & 63;
                        Cout[(((long long)(bb * H_ + h) * D_ + d0) * T_) + t] = cc[r * 2 + jj];
                    }
                }
            } else if (MODE == 1) {
#pragma unroll
                for (int r = 0; r < 2; r++) {
                    float2 f; f.x = cc[r * 2] * 8.0f; f.y = cc[r * 2 + 1] * 8.0f;
                    *(float2*)&Cout[(long long)z * T_ * T_ + (long long)(m + r * 8) * T_ + n] = f;
                }
            } else if (MODE == 2) {
                const int bb = z >> 4, h = z & 15;
#pragma unroll
                for (int r = 0; r < 2; r++) {
                    float2 f; f.x = cc[r * 2]; f.y = cc[r * 2 + 1];
                    *(float2*)&Cout[((long long)(bb * T_ + m + r * 8)) * C_ + h * D_ + n] = f;
                }
            } else {
#pragma unroll
                for (int r = 0; r < 2; r++) {
                    float2 f;
                    f.x = cc[r * 2]     + bias[n];
                    f.y = cc[r * 2 + 1] + bias[n + 1];
                    *(float2*)&Cout[(long long)(m + r * 8) * C_ + n] = f;
                }
            }
        }
    }
}

// ---------------------------------------------------------------------------
// Head-axis softmax (reference quirk: softmax over dim=1 == H).
// ---------------------------------------------------------------------------
__global__ __launch_bounds__(256) void softmax_head_kernel(float* __restrict__ s)
{
    const long long idx = (long long)blockIdx.x * blockDim.x + threadIdx.x;
    const long long hs = (long long)T_ * T_;
    const int kk = (int)(idx & (T_ - 1));
    const long long bq = idx >> 11;
    const int b = (int)(bq >> 11);
    const int q = (int)(bq & (T_ - 1));
    const long long base = (((long long)b * H_) * T_ + q) * T_ + kk;

    float v[H_];
    float mx = -1e30f;
#pragma unroll
    for (int h = 0; h < H_; h++) {
        v[h] = s[base + (long long)h * hs];
        mx = fmaxf(mx, v[h]);
    }
    float sum = 0.0f;
#pragma unroll
    for (int h = 0; h < H_; h++) {
        v[h] = __expf(v[h] - mx);
        sum += v[h];
    }
    const float inv = 1.0f / sum;
#pragma unroll
    for (int h = 0; h < H_; h++)
        s[base + (long long)h * hs] = v[h] * inv;
}

// ---------------------------------------------------------------------------
extern "C" void kernel_launch(void* const* d_in, const int* in_sizes, int n_in,
                              void* d_out, int out_size)
{
    const float* query_src = (const float*)d_in[0];
    const float* key_src   = (const float*)d_in[1];
    const float* value_src = (const float*)d_in[2];
    const float* Wq        = (const float*)d_in[3];
    const float* Wk        = (const float*)d_in[4];
    const float* Wv        = (const float*)d_in[5];
    const float* Wo        = (const float*)d_in[6];
    const float* bo        = (const float*)d_in[7];
    float* out = (float*)d_out;

    float *q, *k, *v, *s, *o;
    cudaGetSymbolAddress((void**)&q, g_q);
    cudaGetSymbolAddress((void**)&k, g_k);
    cudaGetSymbolAddress((void**)&v, g_v);
    cudaGetSymbolAddress((void**)&s, g_s);
    cudaGetSymbolAddress((void**)&o, g_o);

    // smem sizes: (A parts + B parts) * BKP(36) * 4B
    const int SM_SPLIT128  = (2 * 128 + 2 * 128) * 36 * 4;  // 73728
    const int SM_SINGLE128 = (128 + 128) * 36 * 4;          // 36864
    const int SM_SINGLE64  = (128 + 64) * 36 * 4;           // 27648
    cudaFuncSetAttribute(mma_gemm<0, true, 128>, cudaFuncAttributeMaxDynamicSharedMemorySize, SM_SPLIT128);
    cudaFuncSetAttribute(mma_gemm<4, true, 128>, cudaFuncAttributeMaxDynamicSharedMemorySize, SM_SPLIT128);
    cudaFuncSetAttribute(mma_gemm<1, true, 128>, cudaFuncAttributeMaxDynamicSharedMemorySize, SM_SPLIT128);
    cudaFuncSetAttribute(mma_gemm<2, false, 64>, cudaFuncAttributeMaxDynamicSharedMemorySize, SM_SINGLE64);
    cudaFuncSetAttribute(mma_gemm<3, false, 128>, cudaFuncAttributeMaxDynamicSharedMemorySize, SM_SINGLE128);

    const dim3 blk(256);

    // Pass 1: projections y = x @ W^T.  Q,K -> [b,h,t,d]; V -> [b,h,d,t] (split tf32)
    {
        dim3 grid(C_ / 128, (B_ * T_) / 128, 1);
        mma_gemm<0, true, 128><<<grid, blk, SM_SPLIT128>>>(query_src, Wq, q, nullptr, C_, C_, C_, 0, 0);
        mma_gemm<0, true, 128><<<grid, blk, SM_SPLIT128>>>(key_src,   Wk, k, nullptr, C_, C_, C_, 0, 0);
        mma_gemm<4, true, 128><<<grid, blk, SM_SPLIT128>>>(value_src, Wv, v, nullptr, C_, C_, C_, 0, 0);
    }
    // Pass 2: S[b,h,q,k] = 8 * q.k   (split tf32)
    {
        dim3 grid(T_ / 128, T_ / 128, B_ * H_);
        mma_gemm<1, true, 128><<<grid, blk, SM_SPLIT128>>>(q, k, s, nullptr, D_, D_, D_,
                                                           (long long)T_ * D_, (long long)T_ * D_);
    }
    // Pass 3: softmax over HEAD axis (in place)
    {
        const long long total = (long long)B_ * T_ * T_;
        softmax_head_kernel<<<(unsigned)(total / 256), 256>>>(s);
    }
    // Pass 4: O = P @ V^T_stored -> [b][q][h*64+d]   (single tf32, NT vs transposed V)
    {
        dim3 grid(1, T_ / 128, B_ * H_);
        mma_gemm<2, false, 64><<<grid, blk, SM_SINGLE64>>>(s, v, o, nullptr, T_, T_, T_,
                                                           (long long)T_ * T_, (long long)D_ * T_);
    }
    // Pass 5: out = O @ Wo^T + bo   (single tf32)
    {
        dim3 grid(C_ / 128, (B_ * T_) / 128, 1);
        mma_gemm<3, false, 128><<<grid, blk, SM_SINGLE128>>>(o, Wo, out, bo, C_, C_, C_, 0, 0);
    }
}